// round 5
// baseline (speedup 1.0000x reference)
#include <cuda_runtime.h>

// ---------------- problem constants (fixed shapes) ----------------
#define N_SRC1 200000
#define N_DST1 50000
#define N_DST2 10000
#define E1     2000000
#define E2     400000
#define IN_F   128
#define H_F    256
#define N_CLS  47

#define PAD1   50048   // N_DST1 padded to multiple of 128
#define PAD2   10048

// ---------------- scratch (device globals; zero-initialized) ----------------
__device__ int   g_is64;
__device__ int   g_src1[E1];
__device__ int   g_src2[E2];
__device__ int   g_off1[N_DST1 + 1];
__device__ int   g_off2[N_DST2 + 1];
__device__ float g_hneigh1[(size_t)PAD1 * IN_F];   // layer1 mean-aggregated feats
__device__ float g_h[(size_t)PAD1 * H_F];          // layer1 output (relu'd)
__device__ float g_hneigh2[(size_t)PAD2 * H_F];    // layer2 mean-aggregated feats

// ---------------- index dtype detection ----------------
// src1 values are uniform-random in [0, 200000). If the array is int64, every
// odd 32-bit word (the high word) is zero. If int32, odd words are random and
// essentially surely nonzero among 128 samples.
__global__ void detect_kernel(const int* __restrict__ src1_raw) {
    if (threadIdx.x == 0) {
        int nz = 0;
        for (int i = 1; i < 256; i += 2) nz |= (src1_raw[i] != 0);
        g_is64 = nz ? 0 : 1;
    }
}

__global__ void convert1_kernel(const void* __restrict__ src) {
    int i = blockIdx.x * blockDim.x + threadIdx.x;
    if (i >= E1) return;
    if (g_is64) g_src1[i] = (int)((const long long*)src)[i];
    else        g_src1[i] = ((const int*)src)[i];
}
__global__ void convert2_kernel(const void* __restrict__ src) {
    int i = blockIdx.x * blockDim.x + threadIdx.x;
    if (i >= E2) return;
    if (g_is64) g_src2[i] = (int)((const long long*)src)[i];
    else        g_src2[i] = ((const int*)src)[i];
}

template <typename T>
__device__ __forceinline__ int lower_bound_dev(const T* a, int n, long long key) {
    int lo = 0, hi = n;
    while (lo < hi) {
        int mid = (lo + hi) >> 1;
        if ((long long)a[mid] < key) lo = mid + 1; else hi = mid;
    }
    return lo;
}

// dst is sorted: offsets[d] = lower_bound(dst, d). Segment [off[d], off[d+1])
// holds exactly the edges with dst == d.
__global__ void offsets1_kernel(const void* __restrict__ dst) {
    int d = blockIdx.x * blockDim.x + threadIdx.x;
    if (d > N_DST1) return;
    g_off1[d] = g_is64 ? lower_bound_dev((const long long*)dst, E1, (long long)d)
                       : lower_bound_dev((const int*)dst, E1, (long long)d);
}
__global__ void offsets2_kernel(const void* __restrict__ dst) {
    int d = blockIdx.x * blockDim.x + threadIdx.x;
    if (d > N_DST2) return;
    g_off2[d] = g_is64 ? lower_bound_dev((const long long*)dst, E2, (long long)d)
                       : lower_bound_dev((const int*)dst, E2, (long long)d);
}

// ---------------- layer-1 aggregation: one warp per dst, 128 feats ----------------
__global__ __launch_bounds__(256) void agg1_kernel(const float* __restrict__ x) {
    int gw   = (blockIdx.x * 256 + threadIdx.x) >> 5;
    if (gw >= N_DST1) return;
    int lane = threadIdx.x & 31;
    int s = g_off1[gw], e = g_off1[gw + 1];
    float ax = 0.f, ay = 0.f, az = 0.f, aw = 0.f;
    int i = s;
    for (; i + 2 <= e; i += 2) {                 // unroll 2 -> 2 gathers in flight
        int s0 = g_src1[i], s1 = g_src1[i + 1];
        float4 v0 = __ldg(((const float4*)(x + (size_t)s0 * IN_F)) + lane);
        float4 v1 = __ldg(((const float4*)(x + (size_t)s1 * IN_F)) + lane);
        ax += v0.x + v1.x; ay += v0.y + v1.y;
        az += v0.z + v1.z; aw += v0.w + v1.w;
    }
    if (i < e) {
        int s0 = g_src1[i];
        float4 v0 = __ldg(((const float4*)(x + (size_t)s0 * IN_F)) + lane);
        ax += v0.x; ay += v0.y; az += v0.z; aw += v0.w;
    }
    int deg = e - s;
    float sc = 1.0f / (float)(deg > 0 ? deg : 1);
    ((float4*)(g_hneigh1 + (size_t)gw * IN_F))[lane] =
        make_float4(ax * sc, ay * sc, az * sc, aw * sc);
}

// ---------------- layer-2 aggregation: one warp per dst, 256 feats ----------------
__global__ __launch_bounds__(256) void agg2_kernel() {
    int gw   = (blockIdx.x * 256 + threadIdx.x) >> 5;
    if (gw >= N_DST2) return;
    int lane = threadIdx.x & 31;
    int s = g_off2[gw], e = g_off2[gw + 1];
    float4 a0 = make_float4(0.f, 0.f, 0.f, 0.f);
    float4 a1 = make_float4(0.f, 0.f, 0.f, 0.f);
    int i = s;
    for (; i + 2 <= e; i += 2) {
        int s0 = g_src2[i], s1 = g_src2[i + 1];
        const float4* r0 = (const float4*)(g_h + (size_t)s0 * H_F);
        const float4* r1 = (const float4*)(g_h + (size_t)s1 * H_F);
        float4 u0 = r0[lane], u1 = r0[lane + 32];
        float4 w0 = r1[lane], w1 = r1[lane + 32];
        a0.x += u0.x + w0.x; a0.y += u0.y + w0.y; a0.z += u0.z + w0.z; a0.w += u0.w + w0.w;
        a1.x += u1.x + w1.x; a1.y += u1.y + w1.y; a1.z += u1.z + w1.z; a1.w += u1.w + w1.w;
    }
    if (i < e) {
        int s0 = g_src2[i];
        const float4* r0 = (const float4*)(g_h + (size_t)s0 * H_F);
        float4 u0 = r0[lane], u1 = r0[lane + 32];
        a0.x += u0.x; a0.y += u0.y; a0.z += u0.z; a0.w += u0.w;
        a1.x += u1.x; a1.y += u1.y; a1.z += u1.z; a1.w += u1.w;
    }
    int deg = e - s;
    float sc = 1.0f / (float)(deg > 0 ? deg : 1);
    float4* op = (float4*)(g_hneigh2 + (size_t)gw * H_F);
    op[lane]      = make_float4(a0.x * sc, a0.y * sc, a0.z * sc, a0.w * sc);
    op[lane + 32] = make_float4(a1.x * sc, a1.y * sc, a1.z * sc, a1.w * sc);
}

// ---------------- layer-1 fused dual-GEMM + bias + relu ----------------
// g_h[m,n] = relu( x[m,:]@Wself[:,n] + hneigh1[m,:]@Wneigh[:,n] + b1[n] )
// Treated as K=256 concat GEMM. BM=128, BN=128, BK=16, 256 threads, 8x8/thread.
// Inner product uses packed fma.rn.f32x2 (2 FMA/instr; ptxas never emits it).
__global__ __launch_bounds__(256) void gemm1_kernel(
    const float* __restrict__ x, const float* __restrict__ Wself,
    const float* __restrict__ Wneigh, const float* __restrict__ bias1) {
    __shared__ float As[16][136];   // transposed A tile, padded
    __shared__ float Bs[16][128];

    int bm  = blockIdx.x * 128;
    int bn  = blockIdx.y * 128;
    int tid = threadIdx.x;
    int tx  = tid & 15;
    int ty  = tid >> 4;

    unsigned long long acc2[8][4];
    #pragma unroll
    for (int i = 0; i < 8; i++)
        #pragma unroll
        for (int j = 0; j < 4; j++) acc2[i][j] = 0ULL;

    int ar  = tid >> 1;            // A tile row 0..127
    int akc = (tid & 1) * 8;       // A tile k-offset 0 or 8
    int bkr = tid >> 4;            // B tile k-row 0..15
    int bnc = (tid & 15) * 8;      // B tile n-offset

    #pragma unroll 1
    for (int kk = 0; kk < 16; ++kk) {
        const float* A = (kk < 8) ? x : g_hneigh1;          // both stride IN_F=128
        const float* B = (kk < 8) ? Wself : Wneigh;         // stride H_F=256
        int k0 = (kk & 7) * 16;

        const float* ap = A + (size_t)(bm + ar) * IN_F + k0 + akc;
        float4 a0 = *(const float4*)ap;
        float4 a1 = *(const float4*)(ap + 4);
        const float* bp = B + (size_t)(k0 + bkr) * H_F + bn + bnc;
        float4 b0 = *(const float4*)bp;
        float4 b1 = *(const float4*)(bp + 4);

        __syncthreads();
        As[akc + 0][ar] = a0.x; As[akc + 1][ar] = a0.y;
        As[akc + 2][ar] = a0.z; As[akc + 3][ar] = a0.w;
        As[akc + 4][ar] = a1.x; As[akc + 5][ar] = a1.y;
        As[akc + 6][ar] = a1.z; As[akc + 7][ar] = a1.w;
        *(float4*)&Bs[bkr][bnc]     = b0;
        *(float4*)&Bs[bkr][bnc + 4] = b1;
        __syncthreads();

        #pragma unroll
        for (int k = 0; k < 16; k++) {
            float4 af0 = *(const float4*)&As[k][ty * 8];
            float4 af1 = *(const float4*)&As[k][ty * 8 + 4];
            ulonglong2 bq0 = *(const ulonglong2*)&Bs[k][tx * 8];
            ulonglong2 bq1 = *(const ulonglong2*)&Bs[k][tx * 8 + 4];
            unsigned long long bb[4] = {bq0.x, bq0.y, bq1.x, bq1.y};
            float av[8] = {af0.x, af0.y, af0.z, af0.w, af1.x, af1.y, af1.z, af1.w};
            #pragma unroll
            for (int i = 0; i < 8; i++) {
                unsigned long long ad;
                asm("mov.b64 %0, {%1, %1};" : "=l"(ad) : "f"(av[i]));
                #pragma unroll
                for (int j = 0; j < 4; j++)
                    asm("fma.rn.f32x2 %0, %1, %2, %0;"
                        : "+l"(acc2[i][j]) : "l"(ad), "l"(bb[j]));
            }
        }
    }

    // epilogue: bias + relu, write g_h
    float4 bb0 = *(const float4*)&bias1[bn + tx * 8];
    float4 bb1 = *(const float4*)&bias1[bn + tx * 8 + 4];
    float bv[8] = {bb0.x, bb0.y, bb0.z, bb0.w, bb1.x, bb1.y, bb1.z, bb1.w};
    #pragma unroll
    for (int i = 0; i < 8; i++) {
        int m = bm + ty * 8 + i;              // m < PAD1 always (grid covers pad)
        float vals[8];
        #pragma unroll
        for (int j = 0; j < 4; j++) {
            float lo, hi;
            asm("mov.b64 {%0, %1}, %2;" : "=f"(lo), "=f"(hi) : "l"(acc2[i][j]));
            vals[2 * j]     = lo;
            vals[2 * j + 1] = hi;
        }
        float4 r0, r1;
        r0.x = fmaxf(vals[0] + bv[0], 0.f); r0.y = fmaxf(vals[1] + bv[1], 0.f);
        r0.z = fmaxf(vals[2] + bv[2], 0.f); r0.w = fmaxf(vals[3] + bv[3], 0.f);
        r1.x = fmaxf(vals[4] + bv[4], 0.f); r1.y = fmaxf(vals[5] + bv[5], 0.f);
        r1.z = fmaxf(vals[6] + bv[6], 0.f); r1.w = fmaxf(vals[7] + bv[7], 0.f);
        float* op = g_h + (size_t)m * H_F + bn + tx * 8;
        *(float4*)op       = r0;
        *(float4*)(op + 4) = r1;
    }
}

// ---------------- layer-2 fused dual-GEMM + bias (no relu) ----------------
// out[m,n] = h[m,:]@Ws2[:,n] + hneigh2[m,:]@Wn2[:,n] + b2[n], n < 47.
// 32 rows/block, cols padded to 64 lanes; W + A chunks staged in smem.
__global__ __launch_bounds__(256) void gemm2_kernel(
    const float* __restrict__ Ws2, const float* __restrict__ Wn2,
    const float* __restrict__ b2, float* __restrict__ out) {
    __shared__ float sWs[64][48];
    __shared__ float sWn[64][48];
    __shared__ float sAS[32][64];
    __shared__ float sAN[32][64];

    int t    = threadIdx.x;
    int n    = t & 63;
    int rg   = t >> 6;                      // 0..3
    int nc   = (n < N_CLS) ? n : (N_CLS - 1);
    int row0 = blockIdx.x * 32;

    float acc[8];
    #pragma unroll
    for (int i = 0; i < 8; i++) acc[i] = 0.f;

    for (int kt = 0; kt < 4; ++kt) {
        for (int idx = t; idx < 64 * N_CLS; idx += 256) {
            int kk = idx / N_CLS;
            int nn = idx - kk * N_CLS;
            sWs[kk][nn] = Ws2[(kt * 64 + kk) * N_CLS + nn];
            sWn[kk][nn] = Wn2[(kt * 64 + kk) * N_CLS + nn];
        }
        for (int idx = t; idx < 512; idx += 256) {
            int r = idx >> 4;
            int c = (idx & 15) * 4;
            *(float4*)&sAS[r][c] =
                *(const float4*)(g_h + (size_t)(row0 + r) * H_F + kt * 64 + c);
            *(float4*)&sAN[r][c] =
                *(const float4*)(g_hneigh2 + (size_t)(row0 + r) * H_F + kt * 64 + c);
        }
        __syncthreads();
        #pragma unroll 4
        for (int kk = 0; kk < 64; kk++) {
            float ws = sWs[kk][nc];
            float wn = sWn[kk][nc];
            #pragma unroll
            for (int i = 0; i < 8; i++) {
                acc[i] = fmaf(sAS[rg * 8 + i][kk], ws, acc[i]);
                acc[i] = fmaf(sAN[rg * 8 + i][kk], wn, acc[i]);
            }
        }
        __syncthreads();
    }

    if (n < N_CLS) {
        float bb = b2[n];
        #pragma unroll
        for (int i = 0; i < 8; i++) {
            int row = row0 + rg * 8 + i;
            if (row < N_DST2) out[row * N_CLS + n] = acc[i] + bb;
        }
    }
}

// ---------------- launch ----------------
extern "C" void kernel_launch(void* const* d_in, const int* in_sizes, int n_in,
                              void* d_out, int out_size) {
    const float* x       = (const float*)d_in[0];
    const float* Wself1  = (const float*)d_in[1];
    const float* Wneigh1 = (const float*)d_in[2];
    const float* b1      = (const float*)d_in[3];
    const float* Wself2  = (const float*)d_in[4];
    const float* Wneigh2 = (const float*)d_in[5];
    const float* b2      = (const float*)d_in[6];
    const void*  src1    = d_in[7];
    const void*  dst1    = d_in[8];
    const void*  src2    = d_in[9];
    const void*  dst2    = d_in[10];
    float* out = (float*)d_out;

    detect_kernel<<<1, 32>>>((const int*)src1);
    convert1_kernel<<<(E1 + 255) / 256, 256>>>(src1);
    convert2_kernel<<<(E2 + 255) / 256, 256>>>(src2);
    offsets1_kernel<<<(N_DST1 + 1 + 255) / 256, 256>>>(dst1);
    offsets2_kernel<<<(N_DST2 + 1 + 255) / 256, 256>>>(dst2);

    agg1_kernel<<<(N_DST1 + 7) / 8, 256>>>(x);

    dim3 g1(PAD1 / 128, 2);             // 391 x 2 blocks
    gemm1_kernel<<<g1, 256>>>(x, Wself1, Wneigh1, b1);

    agg2_kernel<<<(N_DST2 + 7) / 8, 256>>>();

    gemm2_kernel<<<(N_DST2 + 31) / 32, 256>>>(Wself2, Wneigh2, b2, out);
}